// round 16
// baseline (speedup 1.0000x reference)
#include <cuda_runtime.h>
#include <math_constants.h>
#include <stdint.h>

#define NROWS 16384
#define DIM   256
#define CSIZE 1024
#define NSTAGE 8
#define CAP   24
#define MTILE 64
#define PITCH_A 264            // %32==8 -> conflict-free LDS.64 frags
#define PITCH_B 40             // %32==8
#define NBUF  2
#define NBLK  (NROWS / MTILE)  // 256
// dyn smem layout (words): As | Bs | rowmin | rowcnt
#define OFF_BS     (MTILE * PITCH_A)                    // 16896
#define OFF_RMIN   (OFF_BS + NBUF * 128 * PITCH_B)      // 27136
#define OFF_RCNT   (OFF_RMIN + MTILE)
#define SMEM_DYN   ((OFF_RCNT + MTILE) * 4)             // 109056 B -> 2 CTAs/SM

// Scratch (allocation-free)
__device__ float    g_res[NROWS * DIM];
__device__ float    g_rownorm[NROWS];
__device__ float    g_cbnorm[NSTAGE * CSIZE];
__device__ uint32_t g_cbtf[NSTAGE * CSIZE * DIM];   // tf32 bits, k-permuted
__device__ int      g_cbmax[NSTAGE];
__device__ int2     g_cand2[NROWS * CAP];           // raw captures: {fkey(score), col}
__device__ float    g_losspart[NSTAGE * NBLK];

// ---------- helpers ----------
__device__ __forceinline__ uint32_t smem_u32(const void* p) {
    return (uint32_t)__cvta_generic_to_shared(p);
}
__device__ __forceinline__ void cp_async16(uint32_t saddr, const void* gptr) {
    asm volatile("cp.async.cg.shared.global [%0], [%1], 16;" :: "r"(saddr), "l"(gptr));
}
#define CP_COMMIT() asm volatile("cp.async.commit_group;")
#define CP_WAIT1()  asm volatile("cp.async.wait_group 1;")

__device__ __forceinline__ uint32_t f2tf32(float f) {
    uint32_t r;
    asm("cvt.rna.tf32.f32 %0, %1;" : "=r"(r) : "f"(f));
    return r;
}
__device__ __forceinline__ void mma_tf32(float& c0, float& c1, float& c2, float& c3,
                                         uint32_t a0, uint32_t a1, uint32_t a2, uint32_t a3,
                                         uint32_t b0, uint32_t b1) {
    asm("mma.sync.aligned.m16n8k8.row.col.f32.tf32.tf32.f32 "
        "{%0,%1,%2,%3}, {%4,%5,%6,%7}, {%8,%9}, {%0,%1,%2,%3};"
        : "+f"(c0), "+f"(c1), "+f"(c2), "+f"(c3)
        : "r"(a0), "r"(a1), "r"(a2), "r"(a3), "r"(b0), "r"(b1));
}
__device__ __forceinline__ int fkey(float f) {
    int i = __float_as_int(f);
    return i >= 0 ? i : i ^ 0x7FFFFFFF;
}
__device__ __forceinline__ float funkey(int i) {
    return __int_as_float(i >= 0 ? i : i ^ 0x7FFFFFFF);
}
__device__ __forceinline__ bool lt_vi(float v, int i, float w, int j) {
    return v < w || (v == w && i < j);
}
__device__ __forceinline__ int kperm(int k) {
    return (k & ~7) + 2 * (k & 3) + ((k >> 2) & 1);
}

// ---------- init: x -> res + rownorm (bit-identical chain) ----------
__global__ void init_kernel(const float* __restrict__ x) {
    if (blockIdx.x == 0 && threadIdx.x < NSTAGE) g_cbmax[threadIdx.x] = 0;
    int row  = blockIdx.x * 8 + (threadIdx.x >> 5);
    int lane = threadIdx.x & 31;
    size_t rb = (size_t)row * DIM;
    float acc = 0.0f;
#pragma unroll
    for (int i = 0; i < 8; i++) {
        float v = x[rb + lane + 32 * i];
        g_res[rb + lane + 32 * i] = v;
        acc = fmaf(v, v, acc);
    }
#pragma unroll
    for (int off = 16; off > 0; off >>= 1)
        acc += __shfl_down_sync(0xffffffffu, acc, off);
    if (lane == 0) g_rownorm[row] = acc;
}

// Codeword norms + one-time tf32 pre-conversion (k-permuted layout).
__global__ void cbnorm_kernel(const float* __restrict__ codebooks) {
    int row = blockIdx.x * 8 + (threadIdx.x >> 5);
    int lane = threadIdx.x & 31;
    if (row >= NSTAGE * CSIZE) return;
    const float* p = codebooks + (size_t)row * DIM;
    uint32_t* q = g_cbtf + (size_t)row * DIM;
    float acc = 0.0f;
#pragma unroll
    for (int i = 0; i < 8; i++) {
        int k = lane + 32 * i;
        float v = p[k];
        q[kperm(k)] = f2tf32(v);
        acc = fmaf(v, v, acc);
    }
#pragma unroll
    for (int off = 16; off > 0; off >>= 1)
        acc += __shfl_down_sync(0xffffffffu, acc, off);
    if (lane == 0) {
        g_cbnorm[row] = acc;
        atomicMax(&g_cbmax[row >> 10], __float_as_int(acc));
    }
}

// ---------- stage: tf32 screen + prune + fused exact finish ----------
__global__ void __launch_bounds__(256, 2) stage_kernel(
    const float* __restrict__ codebooks, float* __restrict__ out, int stage)
{
    extern __shared__ uint32_t dyn[];
    uint32_t* As = dyn;
    uint32_t* Bs = dyn + OFF_BS;
    int* rowmin  = (int*)(dyn + OFF_RMIN);
    int* rowcnt  = (int*)(dyn + OFF_RCNT);
    __shared__ float ws[8];

    const uint32_t* cbt = g_cbtf + (size_t)stage * CSIZE * DIM;
    const float*    cbn = g_cbnorm + stage * CSIZE;
    const float*    cbf = codebooks + (size_t)stage * CSIZE * DIM;
    float* enc_out = out + 2;

    const int tid  = threadIdx.x;
    const int lane = tid & 31;
    const int wid  = tid >> 5;
    const int wm   = wid >> 2;
    const int wn   = wid & 3;
    const int g    = lane >> 2;
    const int tg   = lane & 3;
    const int block_row = blockIdx.x * MTILE;

    const uint32_t sA = smem_u32(As);
    const uint32_t sB = smem_u32(Bs);

    if (tid < MTILE) { rowmin[tid] = 0x7F800000; rowcnt[tid] = 0; }

#pragma unroll
    for (int l = 0; l < 16; l++) {
        int idx = tid + l * 256;
        int r  = idx >> 6;
        int c4 = (idx & 63) << 2;
        cp_async16(sA + (uint32_t)(r * PITCH_A + c4) * 4,
                   &g_res[(size_t)(block_row + r) * DIM + c4]);
    }
    CP_COMMIT();

    auto issue_chunk = [&](int cc) {
        int nrow = (cc >> 3) * 128;
        int kt   = (cc & 7) * 32;
        uint32_t bbase = sB + (uint32_t)((cc & 1) * 128 * PITCH_B) * 4;
#pragma unroll
        for (int l = 0; l < 4; l++) {
            int idx = tid + l * 256;
            int r  = idx >> 3;
            int c4 = (idx & 7) << 2;
            cp_async16(bbase + (uint32_t)(r * PITCH_B + c4) * 4,
                       &cbt[(size_t)(nrow + r) * DIM + kt + c4]);
        }
    };
    issue_chunk(0); CP_COMMIT();

    const float cbmaxf = __int_as_float(g_cbmax[stage]);
    int   rloc[4];
    float rn4[4], m2[4];
#pragma unroll
    for (int mi = 0; mi < 2; mi++)
#pragma unroll
        for (int h = 0; h < 2; h++) {
            int j = mi * 2 + h;
            int rl = wm * 32 + mi * 16 + g + h * 8;
            rloc[j] = rl;
            float rv = g_rownorm[block_row + rl];
            rn4[j] = rv;
            m2[j] = 2.0f * 0.00390625f * sqrtf(rv * cbmaxf);
        }

    CP_WAIT1();
#pragma unroll
    for (int l = 0; l < 16; l++) {
        int idx = tid + l * 256;
        int r  = idx >> 6;
        int c4 = (idx & 63) << 2;
        uint4 v = *(uint4*)&As[r * PITCH_A + c4];
        uint32_t t0 = f2tf32(__int_as_float(v.x));
        uint32_t t1 = f2tf32(__int_as_float(v.y));
        uint32_t t2 = f2tf32(__int_as_float(v.z));
        uint32_t t3 = f2tf32(__int_as_float(v.w));
        __syncthreads();
        int kb = c4 & ~7;
        int h  = (c4 >> 2) & 1;
        uint32_t* rowp = &As[r * PITCH_A + kb + h];
        rowp[0] = t0; rowp[2] = t1; rowp[4] = t2; rowp[6] = t3;
        __syncthreads();
    }

    float acc[2][4][4];
#pragma unroll
    for (int mi = 0; mi < 2; mi++)
#pragma unroll
        for (int ni = 0; ni < 4; ni++)
#pragma unroll
            for (int e = 0; e < 4; e++) acc[mi][ni][e] = 0.0f;

    for (int c = 0; c < 64; c++) {
        if (c + 1 < 64) issue_chunk(c + 1);
        CP_COMMIT();
        CP_WAIT1();
        __syncthreads();

        const int kb_base = (c & 7) * 32;
        const uint32_t* Bbuf = Bs + (c & 1) * 128 * PITCH_B;
#pragma unroll
        for (int ks = 0; ks < 4; ks++) {
            const int kbA = kb_base + ks * 8;
            const int kbB = ks * 8;
            uint32_t a[2][4], b[4][2];
#pragma unroll
            for (int mi = 0; mi < 2; mi++) {
                int m = wm * 32 + mi * 16 + g;
                uint2 u0 = *(const uint2*)&As[m * PITCH_A + kbA + 2 * tg];
                uint2 u1 = *(const uint2*)&As[(m + 8) * PITCH_A + kbA + 2 * tg];
                a[mi][0] = u0.x; a[mi][2] = u0.y;
                a[mi][1] = u1.x; a[mi][3] = u1.y;
            }
#pragma unroll
            for (int ni = 0; ni < 4; ni++) {
                int n = wn * 32 + ni * 8 + g;
                uint2 u = *(const uint2*)&Bbuf[n * PITCH_B + kbB + 2 * tg];
                b[ni][0] = u.x; b[ni][1] = u.y;
            }
#pragma unroll
            for (int mi = 0; mi < 2; mi++)
#pragma unroll
                for (int ni = 0; ni < 4; ni++)
                    mma_tf32(acc[mi][ni][0], acc[mi][ni][1], acc[mi][ni][2], acc[mi][ni][3],
                             a[mi][0], a[mi][1], a[mi][2], a[mi][3],
                             b[ni][0], b[ni][1]);
        }
        __syncthreads();

        if ((c & 7) == 7) {
            const int nccol = (c >> 3) * 128;
            float cnv[4][2];
#pragma unroll
            for (int ni = 0; ni < 4; ni++) {
                int cc = nccol + wn * 32 + ni * 8 + tg * 2;
                cnv[ni][0] = cbn[cc];
                cnv[ni][1] = cbn[cc + 1];
            }
            float locmin[4];
#pragma unroll
            for (int j = 0; j < 4; j++) locmin[j] = CUDART_INF_F;
#pragma unroll
            for (int mi = 0; mi < 2; mi++)
#pragma unroll
                for (int ni = 0; ni < 4; ni++)
#pragma unroll
                    for (int h = 0; h < 2; h++)
#pragma unroll
                        for (int w = 0; w < 2; w++) {
                            float s = (rn4[mi * 2 + h] - 2.0f * acc[mi][ni][h * 2 + w]) + cnv[ni][w];
                            if (s < locmin[mi * 2 + h]) locmin[mi * 2 + h] = s;
                        }
#pragma unroll
            for (int j = 0; j < 4; j++) atomicMin(&rowmin[rloc[j]], fkey(locmin[j]));
            __syncthreads();

            float thr[4];
#pragma unroll
            for (int j = 0; j < 4; j++) thr[j] = funkey(rowmin[rloc[j]]) + m2[j];
#pragma unroll
            for (int mi = 0; mi < 2; mi++)
#pragma unroll
                for (int ni = 0; ni < 4; ni++)
#pragma unroll
                    for (int h = 0; h < 2; h++)
#pragma unroll
                        for (int w = 0; w < 2; w++) {
                            int j = mi * 2 + h;
                            float s = (rn4[j] - 2.0f * acc[mi][ni][h * 2 + w]) + cnv[ni][w];
                            if (s < thr[j]) {
                                int col = nccol + wn * 32 + ni * 8 + tg * 2 + w;
                                int p = atomicAdd(&rowcnt[rloc[j]], 1);
                                if (p < CAP)
                                    g_cand2[(size_t)(block_row + rloc[j]) * CAP + p] =
                                        make_int2(fkey(s), col);
                            }
                        }
            __syncthreads();

#pragma unroll
            for (int mi = 0; mi < 2; mi++)
#pragma unroll
                for (int ni = 0; ni < 4; ni++)
#pragma unroll
                    for (int e = 0; e < 4; e++) acc[mi][ni][e] = 0.0f;
        }
    }

    // ======== prune into smem (reuse As; GEMM done) ========
    int* keep = (int*)As;                        // [MTILE][CAP]
    float* rstg = (float*)(As + MTILE * CAP);    // [8 warps][256] res-row scratch
    __syncthreads();                             // As reads done; gmem captures visible
    if (tid < MTILE) {
        int grow = block_row + tid;
        int cnt = rowcnt[tid];
        int kept;
        if (cnt > CAP) {
            kept = 9999;                         // overflow: full exact scan below
        } else {
            float rv = g_rownorm[grow];
            float m2r = 2.0f * 0.00390625f * sqrtf(rv * cbmaxf);
            float thrf = funkey(rowmin[tid]) + m2r;
            kept = 0;
            for (int p = 0; p < cnt; p++) {
                int2 e = g_cand2[(size_t)grow * CAP + p];
                if (funkey(e.x) < thrf)
                    keep[tid * CAP + kept++] = e.y;
            }
        }
        rowcnt[tid] = kept;                      // kept >= 1 always (non-overflow)
    }
    __syncthreads();

    // ======== fused finish: warp handles 8 rows, singleton-dominant ========
    float warp_loss = 0.0f;
    for (int rr = 0; rr < 8; rr++) {
        int row  = wid * 8 + rr;
        int grow = block_row + row;
        size_t rb = (size_t)grow * DIM;
        int cnt = rowcnt[row];

        int besti;
        if (cnt == 1) {
            besti = keep[row * CAP];             // true margin-set singleton => argmin
        } else {
            // stage exact res row into smem scratch (identical bits)
            float* sa = rstg + wid * 256;
#pragma unroll
            for (int i = 0; i < 8; i++)
                sa[lane + 32 * i] = g_res[rb + lane + 32 * i];
            __syncwarp();
            float rn = g_rownorm[grow];
            float bestv = CUDART_INF_F;
            besti = 0x7FFFFFFF;
            if (cnt <= CAP) {
                if (lane < cnt) {
                    int cidx = keep[row * CAP + lane];
                    const float* crow = &cbf[(size_t)cidx * DIM];
                    float t = 0.0f;
#pragma unroll 8
                    for (int k = 0; k < DIM; k++) t = fmaf(sa[k], crow[k], t);
                    bestv = __fadd_rn(__fsub_rn(rn, 2.0f * t), cbn[cidx]);
                    besti = cidx;
                }
            } else {
                // overflow fallback: exact scan (ultra-rare)
                for (int cidx = lane; cidx < CSIZE; cidx += 32) {
                    const float* crow = &cbf[(size_t)cidx * DIM];
                    float t = 0.0f;
#pragma unroll 8
                    for (int k = 0; k < DIM; k++) t = fmaf(sa[k], crow[k], t);
                    float s = __fadd_rn(__fsub_rn(rn, 2.0f * t), cbn[cidx]);
                    if (lt_vi(s, cidx, bestv, besti)) { bestv = s; besti = cidx; }
                }
            }
#pragma unroll
            for (int o = 16; o > 0; o >>= 1) {
                float ov = __shfl_down_sync(0xffffffffu, bestv, o);
                int   oi = __shfl_down_sync(0xffffffffu, besti, o);
                if (lt_vi(ov, oi, bestv, besti)) { bestv = ov; besti = oi; }
            }
            besti = __shfl_sync(0xffffffffu, besti, 0);
        }
        if (lane == 0)
            enc_out[(size_t)grow * NSTAGE + stage] = (float)besti;

        // bit-exact residual update (strided chain order preserved)
        size_t cbb = (size_t)besti * DIM;
        float lacc = 0.0f;
#pragma unroll
        for (int i = 0; i < 8; i++) {
            int d = lane + 32 * i;
            float diff = g_res[rb + d] - cbf[cbb + d];
            g_res[rb + d] = diff;
            lacc = fmaf(diff, diff, lacc);
        }
#pragma unroll
        for (int o = 16; o > 0; o >>= 1)
            lacc += __shfl_down_sync(0xffffffffu, lacc, o);
        if (lane == 0) {
            g_rownorm[grow] = lacc;
            warp_loss += lacc;
        }
    }
    if (lane == 0) ws[wid] = warp_loss;
    __syncthreads();
    if (tid == 0) {
        float t = 0.0f;
#pragma unroll
        for (int w = 0; w < 8; w++) t += ws[w];
        g_losspart[stage * NBLK + blockIdx.x] = t;
    }
}

// ---------- quantised = x - res_final (tolerance-safe reassociation) ----------
__global__ void quant_kernel(const float* __restrict__ x, float* __restrict__ quant) {
    int i = blockIdx.x * blockDim.x + threadIdx.x;
    int stride = gridDim.x * blockDim.x;
    for (; i < NROWS * DIM; i += stride)
        quant[i] = x[i] - g_res[i];
}

// ---------- loss finalize ----------
__global__ void finalize_kernel(float* __restrict__ out) {
    __shared__ float s[256];
    float t = 0.0f;
    for (int i = threadIdx.x; i < NSTAGE * NBLK; i += 256)
        t += g_losspart[i];
    s[threadIdx.x] = t;
    __syncthreads();
    for (int o = 128; o > 0; o >>= 1) {
        if (threadIdx.x < o) s[threadIdx.x] += s[threadIdx.x + o];
        __syncthreads();
    }
    if (threadIdx.x == 0) {
        float loss = s[0] / (float)((size_t)NROWS * DIM);
        out[0] = loss;
        out[1] = loss;
    }
}

extern "C" void kernel_launch(void* const* d_in, const int* in_sizes, int n_in,
                              void* d_out, int out_size) {
    const float* x         = (const float*)d_in[0];
    const float* codebooks = (const float*)d_in[1];
    float* out = (float*)d_out;

    cudaFuncSetAttribute(stage_kernel,
                         cudaFuncAttributeMaxDynamicSharedMemorySize, SMEM_DYN);

    init_kernel<<<NROWS / 8, 256>>>(x);
    cbnorm_kernel<<<(NSTAGE * CSIZE) / 8, 256>>>(codebooks);
    for (int s = 0; s < NSTAGE; s++)
        stage_kernel<<<NBLK, 256, SMEM_DYN>>>(codebooks, out, s);
    quant_kernel<<<512, 256>>>(x, out + 2 + NROWS * NSTAGE);
    finalize_kernel<<<1, 256>>>(out);
}

// round 17
// speedup vs baseline: 1.2432x; 1.2432x over previous
#include <cuda_runtime.h>
#include <math_constants.h>
#include <stdint.h>

#define NROWS 16384
#define DIM   256
#define CSIZE 1024
#define NSTAGE 8
#define CAP   24
#define UBLK  2048             // finish blocks (8 rows each)
#define FCHUNK 4
#define FPITCH 257
#define FWARP  (FCHUNK * FPITCH + FPITCH)
#define FSMEM  (8 * FWARP * 4)                     // 41120 B
#define MTILE 64
#define PITCH_A 264            // %32==8 -> conflict-free LDS.64 frags
#define PITCH_B 40             // %32==8
#define NBUF  2
#define NBLK  (NROWS / MTILE)  // 256
// dyn smem layout (words): As | Bs | rowmin | rowcnt
#define OFF_BS     (MTILE * PITCH_A)
#define OFF_RMIN   (OFF_BS + NBUF * 128 * PITCH_B)
#define OFF_RCNT   (OFF_RMIN + MTILE)
#define SMEM_DYN   ((OFF_RCNT + MTILE) * 4)             // 109056 B -> 2 CTAs/SM

// Scratch (allocation-free)
__device__ float    g_res[NROWS * DIM];
__device__ float    g_rownorm[NROWS];
__device__ float    g_cbnorm[NSTAGE * CSIZE];
__device__ uint32_t g_cbtf[NSTAGE * CSIZE * DIM];   // tf32 bits, k-permuted
__device__ int      g_cbmax[NSTAGE];                // zero-init; atomicMax idempotent across replays
__device__ int2     g_cand2[NROWS * CAP];           // raw captures: {fkey(score), col}
__device__ int      g_candc[NROWS * CAP];           // pruned candidate cols
__device__ int      g_candcnt[NROWS];
__device__ float    g_losspart[NSTAGE * UBLK];

// ---------- helpers ----------
__device__ __forceinline__ uint32_t smem_u32(const void* p) {
    return (uint32_t)__cvta_generic_to_shared(p);
}
__device__ __forceinline__ void cp_async16(uint32_t saddr, const void* gptr) {
    asm volatile("cp.async.cg.shared.global [%0], [%1], 16;" :: "r"(saddr), "l"(gptr));
}
#define CP_COMMIT() asm volatile("cp.async.commit_group;")
#define CP_WAIT1()  asm volatile("cp.async.wait_group 1;")

__device__ __forceinline__ uint32_t f2tf32(float f) {
    uint32_t r;
    asm("cvt.rna.tf32.f32 %0, %1;" : "=r"(r) : "f"(f));
    return r;
}
__device__ __forceinline__ void mma_tf32(float& c0, float& c1, float& c2, float& c3,
                                         uint32_t a0, uint32_t a1, uint32_t a2, uint32_t a3,
                                         uint32_t b0, uint32_t b1) {
    asm("mma.sync.aligned.m16n8k8.row.col.f32.tf32.tf32.f32 "
        "{%0,%1,%2,%3}, {%4,%5,%6,%7}, {%8,%9}, {%0,%1,%2,%3};"
        : "+f"(c0), "+f"(c1), "+f"(c2), "+f"(c3)
        : "r"(a0), "r"(a1), "r"(a2), "r"(a3), "r"(b0), "r"(b1));
}
__device__ __forceinline__ int fkey(float f) {
    int i = __float_as_int(f);
    return i >= 0 ? i : i ^ 0x7FFFFFFF;
}
__device__ __forceinline__ float funkey(int i) {
    return __int_as_float(i >= 0 ? i : i ^ 0x7FFFFFFF);
}
__device__ __forceinline__ bool lt_vi(float v, int i, float w, int j) {
    return v < w || (v == w && i < j);
}
__device__ __forceinline__ int kperm(int k) {
    return (k & ~7) + 2 * (k & 3) + ((k >> 2) & 1);
}

// ---------- prep: init (blocks 0..2047) + cbnorm (blocks 2048..3071) ----------
__global__ void prep_kernel(const float* __restrict__ x,
                            const float* __restrict__ codebooks) {
    int lane = threadIdx.x & 31;
    if (blockIdx.x < NROWS / 8) {
        // init: x -> res + rownorm (bit-identical chain)
        int row = blockIdx.x * 8 + (threadIdx.x >> 5);
        size_t rb = (size_t)row * DIM;
        float acc = 0.0f;
#pragma unroll
        for (int i = 0; i < 8; i++) {
            float v = x[rb + lane + 32 * i];
            g_res[rb + lane + 32 * i] = v;
            acc = fmaf(v, v, acc);
        }
#pragma unroll
        for (int off = 16; off > 0; off >>= 1)
            acc += __shfl_down_sync(0xffffffffu, acc, off);
        if (lane == 0) g_rownorm[row] = acc;
    } else {
        // cbnorm: codeword norms + one-time tf32 pre-conversion (k-permuted)
        int row = (blockIdx.x - NROWS / 8) * 8 + (threadIdx.x >> 5);
        const float* p = codebooks + (size_t)row * DIM;
        uint32_t* q = g_cbtf + (size_t)row * DIM;
        float acc = 0.0f;
#pragma unroll
        for (int i = 0; i < 8; i++) {
            int k = lane + 32 * i;
            float v = p[k];
            q[kperm(k)] = f2tf32(v);
            acc = fmaf(v, v, acc);
        }
#pragma unroll
        for (int off = 16; off > 0; off >>= 1)
            acc += __shfl_down_sync(0xffffffffu, acc, off);
        if (lane == 0) {
            g_cbnorm[row] = acc;
            atomicMax(&g_cbmax[row >> 10], __float_as_int(acc));
        }
    }
}

// ---------- screen: pipelined tf32 GEMM + capture + final prune ----------
__global__ void __launch_bounds__(256, 2) screen_kernel(int stage)
{
    extern __shared__ uint32_t dyn[];
    uint32_t* As = dyn;
    uint32_t* Bs = dyn + OFF_BS;
    int* rowmin  = (int*)(dyn + OFF_RMIN);
    int* rowcnt  = (int*)(dyn + OFF_RCNT);

    const uint32_t* cbt = g_cbtf + (size_t)stage * CSIZE * DIM;
    const float*    cbn = g_cbnorm + stage * CSIZE;

    const int tid  = threadIdx.x;
    const int lane = tid & 31;
    const int wid  = tid >> 5;
    const int wm   = wid >> 2;
    const int wn   = wid & 3;
    const int g    = lane >> 2;
    const int tg   = lane & 3;
    const int block_row = blockIdx.x * MTILE;

    const uint32_t sA = smem_u32(As);
    const uint32_t sB = smem_u32(Bs);

    if (tid < MTILE) { rowmin[tid] = 0x7F800000; rowcnt[tid] = 0; }

#pragma unroll
    for (int l = 0; l < 16; l++) {
        int idx = tid + l * 256;
        int r  = idx >> 6;
        int c4 = (idx & 63) << 2;
        cp_async16(sA + (uint32_t)(r * PITCH_A + c4) * 4,
                   &g_res[(size_t)(block_row + r) * DIM + c4]);
    }
    CP_COMMIT();

    auto issue_chunk = [&](int cc) {
        int nrow = (cc >> 3) * 128;
        int kt   = (cc & 7) * 32;
        uint32_t bbase = sB + (uint32_t)((cc & 1) * 128 * PITCH_B) * 4;
#pragma unroll
        for (int l = 0; l < 4; l++) {
            int idx = tid + l * 256;
            int r  = idx >> 3;
            int c4 = (idx & 7) << 2;
            cp_async16(bbase + (uint32_t)(r * PITCH_B + c4) * 4,
                       &cbt[(size_t)(nrow + r) * DIM + kt + c4]);
        }
    };
    issue_chunk(0); CP_COMMIT();

    const float cbmaxf = __int_as_float(g_cbmax[stage]);
    int   rloc[4];
    float rn4[4], m2[4];
#pragma unroll
    for (int mi = 0; mi < 2; mi++)
#pragma unroll
        for (int h = 0; h < 2; h++) {
            int j = mi * 2 + h;
            int rl = wm * 32 + mi * 16 + g + h * 8;
            rloc[j] = rl;
            float rv = g_rownorm[block_row + rl];
            rn4[j] = rv;
            m2[j] = 2.0f * 0.00390625f * sqrtf(rv * cbmaxf);
        }

    CP_WAIT1();
#pragma unroll
    for (int l = 0; l < 16; l++) {
        int idx = tid + l * 256;
        int r  = idx >> 6;
        int c4 = (idx & 63) << 2;
        uint4 v = *(uint4*)&As[r * PITCH_A + c4];
        uint32_t t0 = f2tf32(__int_as_float(v.x));
        uint32_t t1 = f2tf32(__int_as_float(v.y));
        uint32_t t2 = f2tf32(__int_as_float(v.z));
        uint32_t t3 = f2tf32(__int_as_float(v.w));
        __syncthreads();
        int kb = c4 & ~7;
        int h  = (c4 >> 2) & 1;
        uint32_t* rowp = &As[r * PITCH_A + kb + h];
        rowp[0] = t0; rowp[2] = t1; rowp[4] = t2; rowp[6] = t3;
        __syncthreads();
    }

    float acc[2][4][4];
#pragma unroll
    for (int mi = 0; mi < 2; mi++)
#pragma unroll
        for (int ni = 0; ni < 4; ni++)
#pragma unroll
            for (int e = 0; e < 4; e++) acc[mi][ni][e] = 0.0f;

    for (int c = 0; c < 64; c++) {
        if (c + 1 < 64) issue_chunk(c + 1);
        CP_COMMIT();
        CP_WAIT1();
        __syncthreads();

        const int kb_base = (c & 7) * 32;
        const uint32_t* Bbuf = Bs + (c & 1) * 128 * PITCH_B;
#pragma unroll
        for (int ks = 0; ks < 4; ks++) {
            const int kbA = kb_base + ks * 8;
            const int kbB = ks * 8;
            uint32_t a[2][4], b[4][2];
#pragma unroll
            for (int mi = 0; mi < 2; mi++) {
                int m = wm * 32 + mi * 16 + g;
                uint2 u0 = *(const uint2*)&As[m * PITCH_A + kbA + 2 * tg];
                uint2 u1 = *(const uint2*)&As[(m + 8) * PITCH_A + kbA + 2 * tg];
                a[mi][0] = u0.x; a[mi][2] = u0.y;
                a[mi][1] = u1.x; a[mi][3] = u1.y;
            }
#pragma unroll
            for (int ni = 0; ni < 4; ni++) {
                int n = wn * 32 + ni * 8 + g;
                uint2 u = *(const uint2*)&Bbuf[n * PITCH_B + kbB + 2 * tg];
                b[ni][0] = u.x; b[ni][1] = u.y;
            }
#pragma unroll
            for (int mi = 0; mi < 2; mi++)
#pragma unroll
                for (int ni = 0; ni < 4; ni++)
                    mma_tf32(acc[mi][ni][0], acc[mi][ni][1], acc[mi][ni][2], acc[mi][ni][3],
                             a[mi][0], a[mi][1], a[mi][2], a[mi][3],
                             b[ni][0], b[ni][1]);
        }
        __syncthreads();

        if ((c & 7) == 7) {
            const int nccol = (c >> 3) * 128;
            float cnv[4][2];
#pragma unroll
            for (int ni = 0; ni < 4; ni++) {
                int cc = nccol + wn * 32 + ni * 8 + tg * 2;
                cnv[ni][0] = cbn[cc];
                cnv[ni][1] = cbn[cc + 1];
            }
            float locmin[4];
#pragma unroll
            for (int j = 0; j < 4; j++) locmin[j] = CUDART_INF_F;
#pragma unroll
            for (int mi = 0; mi < 2; mi++)
#pragma unroll
                for (int ni = 0; ni < 4; ni++)
#pragma unroll
                    for (int h = 0; h < 2; h++)
#pragma unroll
                        for (int w = 0; w < 2; w++) {
                            float s = (rn4[mi * 2 + h] - 2.0f * acc[mi][ni][h * 2 + w]) + cnv[ni][w];
                            if (s < locmin[mi * 2 + h]) locmin[mi * 2 + h] = s;
                        }
#pragma unroll
            for (int j = 0; j < 4; j++) atomicMin(&rowmin[rloc[j]], fkey(locmin[j]));
            __syncthreads();

            float thr[4];
#pragma unroll
            for (int j = 0; j < 4; j++) thr[j] = funkey(rowmin[rloc[j]]) + m2[j];
#pragma unroll
            for (int mi = 0; mi < 2; mi++)
#pragma unroll
                for (int ni = 0; ni < 4; ni++)
#pragma unroll
                    for (int h = 0; h < 2; h++)
#pragma unroll
                        for (int w = 0; w < 2; w++) {
                            int j = mi * 2 + h;
                            float s = (rn4[j] - 2.0f * acc[mi][ni][h * 2 + w]) + cnv[ni][w];
                            if (s < thr[j]) {
                                int col = nccol + wn * 32 + ni * 8 + tg * 2 + w;
                                int p = atomicAdd(&rowcnt[rloc[j]], 1);
                                if (p < CAP)
                                    g_cand2[(size_t)(block_row + rloc[j]) * CAP + p] =
                                        make_int2(fkey(s), col);
                            }
                        }
            __syncthreads();

#pragma unroll
            for (int mi = 0; mi < 2; mi++)
#pragma unroll
                for (int ni = 0; ni < 4; ni++)
#pragma unroll
                    for (int e = 0; e < 4; e++) acc[mi][ni][e] = 0.0f;
        }
    }

    // ---- final prune: re-threshold against the FINAL min + m2 ----
    if (tid < MTILE) {
        int grow = block_row + tid;
        int cnt = rowcnt[tid];
        if (cnt > CAP) {
            g_candcnt[grow] = 9999;        // overflow: full exact scan downstream
        } else {
            float rv = g_rownorm[grow];
            float m2r = 2.0f * 0.00390625f * sqrtf(rv * cbmaxf);
            float thrf = funkey(rowmin[tid]) + m2r;
            int kept = 0;
            for (int p = 0; p < cnt; p++) {
                int2 e = g_cand2[(size_t)grow * CAP + p];
                if (funkey(e.x) < thrf)
                    g_candc[grow * CAP + kept++] = e.y;
            }
            g_candcnt[grow] = kept;        // kept >= 1 always
        }
    }
}

// ---------- finish: singleton-dominant rescreen + update (+quant at last stage) ----------
__global__ void finish_kernel(const float* __restrict__ codebooks,
                              const float* __restrict__ x,
                              float* __restrict__ out, int stage)
{
    extern __shared__ float cs[];
    __shared__ float ws[8];

    const float* cb  = codebooks + (size_t)stage * CSIZE * DIM;
    const float* cbn = g_cbnorm + stage * CSIZE;
    float* enc_out = out + 2;
    float* quant   = out + 2 + NROWS * NSTAGE;

    int wid  = threadIdx.x >> 5;
    int lane = threadIdx.x & 31;
    int row  = blockIdx.x * 8 + wid;
    size_t rb = (size_t)row * DIM;

    int   cnt = g_candcnt[row];
    int   c0  = g_candc[row * CAP];
    float rn  = g_rownorm[row];
    float a[8];
#pragma unroll
    for (int i = 0; i < 8; i++)
        a[i] = g_res[rb + lane + 32 * i];

    int besti;
    if (cnt == 1) {
        besti = c0;                        // true margin-set singleton => argmin
    } else {
        float* my = cs + wid * FWARP;
        float* sa = my + FCHUNK * FPITCH;
#pragma unroll
        for (int i = 0; i < 8; i++)
            sa[lane + 32 * i] = a[i];
        __syncwarp();

        float bestv = CUDART_INF_F;
        besti = 0x7FFFFFFF;
        if (cnt <= CAP) {
            for (int base = 0; base < cnt; base += FCHUNK) {
                int nc = min(FCHUNK, cnt - base);
                for (int j = 0; j < nc; j++) {
                    const float* crow = &cb[(size_t)g_candc[row * CAP + base + j] * DIM];
#pragma unroll
                    for (int i = 0; i < 8; i++)
                        my[j * FPITCH + lane + 32 * i] = crow[lane + 32 * i];
                }
                __syncwarp();
                if (lane < nc) {
                    int cidx = g_candc[row * CAP + base + lane];
                    const float* srow = my + lane * FPITCH;
                    float t = 0.0f;
#pragma unroll 8
                    for (int k = 0; k < DIM; k++) t = fmaf(sa[k], srow[k], t);
                    float s = __fadd_rn(__fsub_rn(rn, 2.0f * t), cbn[cidx]);
                    if (lt_vi(s, cidx, bestv, besti)) { bestv = s; besti = cidx; }
                }
                __syncwarp();
            }
        } else {
            for (int cidx = lane; cidx < CSIZE; cidx += 32) {
                const float* crow = &cb[(size_t)cidx * DIM];
                float t = 0.0f;
#pragma unroll 8
                for (int k = 0; k < DIM; k++) t = fmaf(sa[k], crow[k], t);
                float s = __fadd_rn(__fsub_rn(rn, 2.0f * t), cbn[cidx]);
                if (lt_vi(s, cidx, bestv, besti)) { bestv = s; besti = cidx; }
            }
        }
#pragma unroll
        for (int o = 16; o > 0; o >>= 1) {
            float ov = __shfl_down_sync(0xffffffffu, bestv, o);
            int   oi = __shfl_down_sync(0xffffffffu, besti, o);
            if (lt_vi(ov, oi, bestv, besti)) { bestv = ov; besti = oi; }
        }
        besti = __shfl_sync(0xffffffffu, besti, 0);
    }
    if (lane == 0)
        enc_out[(size_t)row * NSTAGE + stage] = (float)besti;

    size_t cbb = (size_t)besti * DIM;
    float lacc = 0.0f;
#pragma unroll
    for (int i = 0; i < 8; i++) {
        int d = lane + 32 * i;
        float diff = a[i] - cb[cbb + d];
        g_res[rb + d] = diff;
        if (stage == NSTAGE - 1)
            quant[rb + d] = x[rb + d] - diff;   // quantised = x - res_final
        lacc = fmaf(diff, diff, lacc);
    }
#pragma unroll
    for (int o = 16; o > 0; o >>= 1)
        lacc += __shfl_down_sync(0xffffffffu, lacc, o);
    if (lane == 0) {
        g_rownorm[row] = lacc;
        ws[wid] = lacc;
    }
    __syncthreads();
    if (threadIdx.x == 0) {
        float t = 0.0f;
#pragma unroll
        for (int w = 0; w < 8; w++) t += ws[w];
        g_losspart[stage * UBLK + blockIdx.x] = t;
    }
}

// ---------- loss finalize ----------
__global__ void finalize_kernel(float* __restrict__ out) {
    __shared__ float s[256];
    float t = 0.0f;
    for (int i = threadIdx.x; i < NSTAGE * UBLK; i += 256)
        t += g_losspart[i];
    s[threadIdx.x] = t;
    __syncthreads();
    for (int o = 128; o > 0; o >>= 1) {
        if (threadIdx.x < o) s[threadIdx.x] += s[threadIdx.x + o];
        __syncthreads();
    }
    if (threadIdx.x == 0) {
        float loss = s[0] / (float)((size_t)NROWS * DIM);
        out[0] = loss;
        out[1] = loss;
    }
}

extern "C" void kernel_launch(void* const* d_in, const int* in_sizes, int n_in,
                              void* d_out, int out_size) {
    const float* x         = (const float*)d_in[0];
    const float* codebooks = (const float*)d_in[1];
    float* out = (float*)d_out;

    cudaFuncSetAttribute(screen_kernel,
                         cudaFuncAttributeMaxDynamicSharedMemorySize, SMEM_DYN);
    cudaFuncSetAttribute(finish_kernel,
                         cudaFuncAttributeMaxDynamicSharedMemorySize, FSMEM);

    prep_kernel<<<NROWS / 8 + (NSTAGE * CSIZE) / 8, 256>>>(x, codebooks);
    for (int s = 0; s < NSTAGE; s++) {
        screen_kernel<<<NBLK, 256, SMEM_DYN>>>(s);
        finish_kernel<<<UBLK, 256, FSMEM>>>(codebooks, x, out, s);
    }
    finalize_kernel<<<1, 256>>>(out);
}